// round 4
// baseline (speedup 1.0000x reference)
#include <cuda_runtime.h>

#define N_GRAPH_C 4096
#define N_NODES_C 131072
#define N_EDGES_C 2097152

#define NT 16384
#define TBL_SCALE 2048.0f            // NT / 8.0
#define TBL_INV_SCALE 4.8828125e-4f  // 8.0 / NT
#define INV_SQRT3_C 0.5773502691896258f
#define INV_SQRT2_C 0.7071067811865476f

// ---------------- persistent device scratch ----------------
// Tables (value + forward-difference slope, rebuilt every launch):
//  g_T1[k*4 + {0,1}] = {A0,A1} values, [k*4 + {2,3}] = slopes
//    A0[o] = sum_c w_si2_0[o,c]*w_si1[c]*R0[c](d)  (layer1 l0, fully folded)
//    A1[o] = sum_c w_si2_1[o,c]*w_si1[c]*R1[c](d)  (layer1 l1, fully folded)
//  g_T2[k*10 + {0..4}] = {R2, R3, R4, R5/sqrt3, R6/sqrt2} values, [+ {5..9}] = slopes
//  g_T3[k*4 + {0,1}]   = {R7, R8/sqrt3} values, [+ {2,3}] = slopes
__device__ float4 g_T1[NT*4];
__device__ float4 g_T2[NT*10];
__device__ float4 g_T3[NT*4];
// Per-edge cached geometry: {ux, uy, uz, fid = d*TBL_SCALE}
__device__ float4 g_geo[N_EDGES_C];
// Accumulators (post self-interaction, pre-gate)
__device__ float4 g_acc1[N_NODES_C*4];
__device__ float4 g_acc2[N_NODES_C*4];
__device__ float4 g_acc3[N_NODES_C];
// Gated features: [0..3]=l0, [4..15]=l1 (layout i*3+m)
__device__ float4 g_feats1[N_NODES_C*4];
__device__ float4 g_feats2[N_NODES_C*4];

// ---------------- helpers ----------------
__device__ __forceinline__ void red_v4(float4* p, float a, float b, float c, float d){
  asm volatile("red.global.add.v4.f32 [%0], {%1,%2,%3,%4};"
               :: "l"(p), "f"(a), "f"(b), "f"(c), "f"(d) : "memory");
}
__device__ __forceinline__ float siluf(float x){ return x / (1.f + __expf(-x)); }
__device__ __forceinline__ float sigmf(float x){ return 1.f / (1.f + __expf(-x)); }
__device__ __forceinline__ float4 vslope4(float4 v, float4 s, float w){
  return make_float4(fmaf(w, s.x, v.x), fmaf(w, s.y, v.y),
                     fmaf(w, s.z, v.z), fmaf(w, s.w, v.w));
}
__device__ __forceinline__ void tbl_decode(float fid, int& i0, float& w){
  int i = (int)fid;
  i = (i > NT-2) ? (NT-2) : i;
  i0 = i;
  w = fminf(fid - (float)i, 1.f);
}

// ---------------- radial MLP eval (table build only) ----------------
__device__ __forceinline__ void eval_R(int p, float d,
                                       const float* __restrict__ rw1, const float* __restrict__ rb1,
                                       const float* __restrict__ rw2, const float* __restrict__ rb2,
                                       float R[4])
{
  float rbf[8];
  #pragma unroll
  for (int j=0;j<8;j++){ float t = d - 0.5f*(float)j; rbf[j] = __expf(-4.f*t*t); }
  float h[8];
  #pragma unroll
  for (int j=0;j<8;j++){
    float a = __ldg(rb1 + p*8 + j);
    #pragma unroll
    for (int b=0;b<8;b++) a = fmaf(rbf[b], __ldg(rw1 + p*64 + b*8 + j), a);
    h[j] = fmaxf(a, 0.f);
  }
  #pragma unroll
  for (int c=0;c<4;c++){
    float a = __ldg(rb2 + p*4 + c);
    #pragma unroll
    for (int j=0;j<8;j++) a = fmaf(h[j], __ldg(rw2 + p*32 + j*4 + c), a);
    R[c] = a;
  }
}

// ---------------- build tables + zero acc1 (fused) ----------------
__global__ void build_zero_kernel(const float* __restrict__ rw1, const float* __restrict__ rb1,
                                  const float* __restrict__ rw2, const float* __restrict__ rb2,
                                  const float* __restrict__ wsi1,
                                  const float* __restrict__ w20, const float* __restrict__ w21)
{
  int idx = blockIdx.x*blockDim.x + threadIdx.x;
  // zeroing part (524288 float4)
  if (idx < N_NODES_C*4) g_acc1[idx] = make_float4(0.f,0.f,0.f,0.f);
  // table part (9*NT threads)
  if (idx >= 9*NT) return;
  int p = idx / NT;
  int k = idx - p*NT;
  float d0 = (float)k * TBL_INV_SCALE;
  float d1 = (float)(k+1) * TBL_INV_SCALE;
  float Ra[4], Rb[4];
  eval_R(p, d0, rw1, rb1, rw2, rb2, Ra);
  eval_R(p, d1, rw1, rb1, rw2, rb2, Rb);

  if (p <= 1){
    const float* W = (p==0) ? w20 : w21;
    float Av[4], As[4];
    #pragma unroll
    for (int o=0;o<4;o++){
      float av = 0.f, ab = 0.f;
      #pragma unroll
      for (int c=0;c<4;c++){
        float wc = __ldg(W + o*4 + c) * __ldg(wsi1 + c);
        av = fmaf(wc, Ra[c], av);
        ab = fmaf(wc, Rb[c], ab);
      }
      Av[o] = av; As[o] = ab - av;
    }
    g_T1[k*4 + p]     = make_float4(Av[0],Av[1],Av[2],Av[3]);
    g_T1[k*4 + 2 + p] = make_float4(As[0],As[1],As[2],As[3]);
  } else if (p <= 6){
    float s = (p==5) ? INV_SQRT3_C : ((p==6) ? INV_SQRT2_C : 1.f);
    int q = p-2;
    g_T2[k*10 + q]     = make_float4(Ra[0]*s, Ra[1]*s, Ra[2]*s, Ra[3]*s);
    g_T2[k*10 + 5 + q] = make_float4((Rb[0]-Ra[0])*s, (Rb[1]-Ra[1])*s,
                                     (Rb[2]-Ra[2])*s, (Rb[3]-Ra[3])*s);
  } else {
    float s = (p==8) ? INV_SQRT3_C : 1.f;
    int q = p-7;
    g_T3[k*4 + q]     = make_float4(Ra[0]*s, Ra[1]*s, Ra[2]*s, Ra[3]*s);
    g_T3[k*4 + 2 + q] = make_float4((Rb[0]-Ra[0])*s, (Rb[1]-Ra[1])*s,
                                    (Rb[2]-Ra[2])*s, (Rb[3]-Ra[3])*s);
  }
}

// ---------------- layer 1 edge kernel (computes + caches geometry) ----------------
__global__ __launch_bounds__(256, 2)
void edge1_kernel(const float* __restrict__ pos, const float* __restrict__ nf,
                  const int* __restrict__ snd, const int* __restrict__ rcv)
{
  int stride = gridDim.x*blockDim.x;
  for (int e = blockIdx.x*blockDim.x + threadIdx.x; e < N_EDGES_C; e += stride){
    int s = __ldg(snd+e), r = __ldg(rcv+e);
    float nv = __ldg(nf + s);
    float ax=__ldg(pos+3*s), ay=__ldg(pos+3*s+1), az=__ldg(pos+3*s+2);
    float bx=__ldg(pos+3*r), by=__ldg(pos+3*r+1), bz=__ldg(pos+3*r+2);
    float dx=bx-ax, dy=by-ay, dz=bz-az;
    float d = sqrtf(dx*dx + dy*dy + dz*dz);
    float inv = 1.f / fmaxf(d, 1e-9f);
    float ux = dx*inv, uy = dy*inv, uz = dz*inv;
    float fid = d * TBL_SCALE;
    g_geo[e] = make_float4(ux, uy, uz, fid);

    int i0; float w; tbl_decode(fid, i0, w);
    const float4* t = &g_T1[(size_t)i0*4];
    float4 A0 = vslope4(__ldg(t+0), __ldg(t+2), w);
    float4 A1 = vslope4(__ldg(t+1), __ldg(t+3), w);
    float4* dst = &g_acc1[(size_t)r*4];
    red_v4(dst, nv*A0.x, nv*A0.y, nv*A0.z, nv*A0.w);
    float t0=nv*A1.x, t1=nv*A1.y, t2=nv*A1.z, t3=nv*A1.w;
    red_v4(dst+1, t0*ux, t0*uy, t0*uz, t1*ux);
    red_v4(dst+2, t1*uy, t1*uz, t2*ux, t2*uy);
    red_v4(dst+3, t2*uz, t3*ux, t3*uy, t3*uz);
  }
}

// ---------------- layer 2 edge kernel ----------------
__global__ __launch_bounds__(256, 2)
void edge2_kernel(const int* __restrict__ snd, const int* __restrict__ rcv,
                  const float* __restrict__ w30, const float* __restrict__ w31)
{
  float W0[32];
  #pragma unroll
  for (int i=0;i<32;i++) W0[i] = __ldg(w30+i);
  float W1[48];
  #pragma unroll
  for (int i=0;i<48;i++) W1[i] = __ldg(w31+i);

  int stride = gridDim.x*blockDim.x;
  for (int e = blockIdx.x*blockDim.x + threadIdx.x; e < N_EDGES_C; e += stride){
    int s = __ldg(snd+e), r = __ldg(rcv+e);
    float4 geo = __ldg(&g_geo[e]);
    float ux = geo.x, uy = geo.y, uz = geo.z;
    int i0; float w; tbl_decode(geo.w, i0, w);

    float4 f0v = __ldg(&g_feats1[(size_t)s*4]);
    float4 fa  = __ldg(&g_feats1[(size_t)s*4+1]);
    float4 fb  = __ldg(&g_feats1[(size_t)s*4+2]);
    float4 fc  = __ldg(&g_feats1[(size_t)s*4+3]);
    float x0[4]  = {f0v.x,f0v.y,f0v.z,f0v.w};
    float x1[12] = {fa.x,fa.y,fa.z,fa.w, fb.x,fb.y,fb.z,fb.w, fc.x,fc.y,fc.z,fc.w};

    const float4* t = &g_T2[(size_t)i0*10];
    float4 r2 = vslope4(__ldg(t+0), __ldg(t+5), w);
    float4 r3 = vslope4(__ldg(t+1), __ldg(t+6), w);
    float4 r4 = vslope4(__ldg(t+2), __ldg(t+7), w);
    float4 r5 = vslope4(__ldg(t+3), __ldg(t+8), w);   // pre-scaled 1/sqrt3
    float4 r6 = vslope4(__ldg(t+4), __ldg(t+9), w);   // pre-scaled 1/sqrt2
    float R2[4]={r2.x,r2.y,r2.z,r2.w}, R3[4]={r3.x,r3.y,r3.z,r3.w};
    float R4[4]={r4.x,r4.y,r4.z,r4.w}, R5[4]={r5.x,r5.y,r5.z,r5.w};
    float R6[4]={r6.x,r6.y,r6.z,r6.w};

    float dot_[4];
    #pragma unroll
    for (int i=0;i<4;i++)
      dot_[i] = x1[i*3]*ux + x1[i*3+1]*uy + x1[i*3+2]*uz;

    // l0: W0 @ [R2*x0 ; R5*dot/sqrt3]
    float ma[4], mb[4];
    #pragma unroll
    for (int i=0;i<4;i++){ ma[i] = R2[i]*x0[i]; mb[i] = R5[i]*dot_[i]; }
    float o0[4];
    #pragma unroll
    for (int o=0;o<4;o++){
      float a = 0.f;
      #pragma unroll
      for (int i=0;i<4;i++){
        a = fmaf(W0[o*8+i],   ma[i], a);
        a = fmaf(W0[o*8+4+i], mb[i], a);
      }
      o0[o] = a;
    }
    float4* dst = &g_acc2[(size_t)r*4];
    red_v4(dst, o0[0], o0[1], o0[2], o0[3]);

    // l1: W1 @ [R3*x0*u ; R4*x1 ; R6*cross(x1,u)/sqrt2]
    float c3[4], e4[12], e6[12];
    #pragma unroll
    for (int i=0;i<4;i++){
      c3[i] = R3[i]*x0[i];
      e4[i*3+0]=R4[i]*x1[i*3+0]; e4[i*3+1]=R4[i]*x1[i*3+1]; e4[i*3+2]=R4[i]*x1[i*3+2];
      e6[i*3+0]=R6[i]*x1[i*3+0]; e6[i*3+1]=R6[i]*x1[i*3+1]; e6[i*3+2]=R6[i]*x1[i*3+2];
    }
    float o1[12];
    #pragma unroll
    for (int o=0;o<4;o++){
      float ta=0.f, zx=0.f, zy=0.f, zz=0.f, yx=0.f, yy=0.f, yz=0.f;
      #pragma unroll
      for (int i=0;i<4;i++){
        ta = fmaf(W1[o*12+i], c3[i], ta);
        float w4 = W1[o*12+4+i], w6 = W1[o*12+8+i];
        zx = fmaf(w4, e4[i*3+0], zx); zy = fmaf(w4, e4[i*3+1], zy); zz = fmaf(w4, e4[i*3+2], zz);
        yx = fmaf(w6, e6[i*3+0], yx); yy = fmaf(w6, e6[i*3+1], yy); yz = fmaf(w6, e6[i*3+2], yz);
      }
      float cx = yy*uz - yz*uy;
      float cy = yz*ux - yx*uz;
      float cz = yx*uy - yy*ux;
      o1[o*3+0] = fmaf(ta, ux, zx + cx);
      o1[o*3+1] = fmaf(ta, uy, zy + cy);
      o1[o*3+2] = fmaf(ta, uz, zz + cz);
    }
    red_v4(dst+1, o1[0], o1[1], o1[2],  o1[3]);
    red_v4(dst+2, o1[4], o1[5], o1[6],  o1[7]);
    red_v4(dst+3, o1[8], o1[9], o1[10], o1[11]);
  }
}

// ---------------- layer 3 edge kernel ----------------
__global__ __launch_bounds__(256, 2)
void edge3_kernel(const int* __restrict__ snd, const int* __restrict__ rcv,
                  const float* __restrict__ w4)
{
  float W4[32];
  #pragma unroll
  for (int i=0;i<32;i++) W4[i] = __ldg(w4+i);

  int stride = gridDim.x*blockDim.x;
  for (int e = blockIdx.x*blockDim.x + threadIdx.x; e < N_EDGES_C; e += stride){
    int s = __ldg(snd+e), r = __ldg(rcv+e);
    float4 geo = __ldg(&g_geo[e]);
    float ux = geo.x, uy = geo.y, uz = geo.z;
    int i0; float w; tbl_decode(geo.w, i0, w);

    float4 f0v = __ldg(&g_feats2[(size_t)s*4]);
    float4 fa  = __ldg(&g_feats2[(size_t)s*4+1]);
    float4 fb  = __ldg(&g_feats2[(size_t)s*4+2]);
    float4 fc  = __ldg(&g_feats2[(size_t)s*4+3]);
    float x0[4]  = {f0v.x,f0v.y,f0v.z,f0v.w};
    float x1[12] = {fa.x,fa.y,fa.z,fa.w, fb.x,fb.y,fb.z,fb.w, fc.x,fc.y,fc.z,fc.w};

    const float4* t = &g_T3[(size_t)i0*4];
    float4 r7 = vslope4(__ldg(t+0), __ldg(t+2), w);
    float4 r8 = vslope4(__ldg(t+1), __ldg(t+3), w);  // pre-scaled 1/sqrt3
    float R7[4]={r7.x,r7.y,r7.z,r7.w}, R8[4]={r8.x,r8.y,r8.z,r8.w};

    float dot_[4];
    #pragma unroll
    for (int i=0;i<4;i++)
      dot_[i] = x1[i*3]*ux + x1[i*3+1]*uy + x1[i*3+2]*uz;

    float o[4];
    #pragma unroll
    for (int oo=0;oo<4;oo++){
      float a = 0.f;
      #pragma unroll
      for (int i=0;i<4;i++){
        a = fmaf(W4[oo*8+i],   R7[i]*x0[i],   a);
        a = fmaf(W4[oo*8+4+i], R8[i]*dot_[i], a);
      }
      o[oo] = a;
    }
    red_v4(&g_acc3[r], o[0], o[1], o[2], o[3]);
  }
}

// ---------------- node gating (layers 1 & 2); zeroes next accumulator ----------------
template<int L>
__global__ void node_gate_kernel(){
  int n = blockIdx.x*blockDim.x + threadIdx.x;
  if (n >= N_NODES_C) return;
  const float4* acc = (L==1) ? g_acc1 : g_acc2;
  float4* fe = (L==1) ? g_feats1 : g_feats2;
  float4 s0 = acc[(size_t)n*4+0];
  float4 s1 = acc[(size_t)n*4+1];
  float4 s2 = acc[(size_t)n*4+2];
  float4 s3 = acc[(size_t)n*4+3];
  float f1[12] = {s1.x,s1.y,s1.z,s1.w, s2.x,s2.y,s2.z,s2.w, s3.x,s3.y,s3.z,s3.w};
  float o1[12];
  #pragma unroll
  for (int o=0;o<4;o++){
    float a=f1[o*3], b=f1[o*3+1], c=f1[o*3+2];
    float nrm = sqrtf(a*a + b*b + c*c);
    float sg = sigmf(nrm);
    o1[o*3+0]=a*sg; o1[o*3+1]=b*sg; o1[o*3+2]=c*sg;
  }
  fe[(size_t)n*4+0] = make_float4(siluf(s0.x), siluf(s0.y), siluf(s0.z), siluf(s0.w));
  fe[(size_t)n*4+1] = make_float4(o1[0],o1[1],o1[2],o1[3]);
  fe[(size_t)n*4+2] = make_float4(o1[4],o1[5],o1[6],o1[7]);
  fe[(size_t)n*4+3] = make_float4(o1[8],o1[9],o1[10],o1[11]);
  // zero the accumulator used by the NEXT edge kernel
  float4 z = make_float4(0.f,0.f,0.f,0.f);
  if (L==1){
    g_acc2[(size_t)n*4+0]=z; g_acc2[(size_t)n*4+1]=z;
    g_acc2[(size_t)n*4+2]=z; g_acc2[(size_t)n*4+3]=z;
  } else {
    g_acc3[n] = z;
  }
}

// ---------------- graph pooling (+silu gate of layer 3) + output projection ----------------
__global__ void pool_kernel(const float* __restrict__ w_out, float* __restrict__ out){
  int gw   = (blockIdx.x*blockDim.x + threadIdx.x) >> 5;
  int lane = threadIdx.x & 31;
  if (gw >= N_GRAPH_C) return;
  float4 a = g_acc3[(size_t)gw*32 + lane];
  float4 v = make_float4(siluf(a.x), siluf(a.y), siluf(a.z), siluf(a.w));
  #pragma unroll
  for (int off=16; off; off>>=1){
    v.x += __shfl_down_sync(0xFFFFFFFFu, v.x, off);
    v.y += __shfl_down_sync(0xFFFFFFFFu, v.y, off);
    v.z += __shfl_down_sync(0xFFFFFFFFu, v.z, off);
    v.w += __shfl_down_sync(0xFFFFFFFFu, v.w, off);
  }
  if (lane == 0){
    #pragma unroll
    for (int j=0;j<8;j++){
      out[gw*8+j] = __ldg(w_out+j*4+0)*v.x + __ldg(w_out+j*4+1)*v.y
                  + __ldg(w_out+j*4+2)*v.z + __ldg(w_out+j*4+3)*v.w;
    }
  }
}

// ---------------- launch ----------------
extern "C" void kernel_launch(void* const* d_in, const int* in_sizes, int n_in,
                              void* d_out, int out_size)
{
  const float* positions = (const float*)d_in[0];
  const float* node_feat = (const float*)d_in[1];
  const float* w_si1     = (const float*)d_in[2];
  const float* w_si2_0   = (const float*)d_in[3];
  const float* w_si2_1   = (const float*)d_in[4];
  const float* w_si3_0   = (const float*)d_in[5];
  const float* w_si3_1   = (const float*)d_in[6];
  const float* w_si4     = (const float*)d_in[7];
  const float* w_out     = (const float*)d_in[8];
  const float* rad_w1    = (const float*)d_in[9];
  const float* rad_b1    = (const float*)d_in[10];
  const float* rad_w2    = (const float*)d_in[11];
  const float* rad_b2    = (const float*)d_in[12];
  const int*   senders   = (const int*)d_in[13];
  const int*   receivers = (const int*)d_in[14];
  float* out = (float*)d_out;

  const int EB = 2048, ET = 256;     // edge kernels: grid-stride, 4 edges/thread
  const int NB = N_NODES_C / 256;

  // fused: zero acc1 (524288 float4 threads) + build tables (first 9*NT threads)
  build_zero_kernel<<<(N_NODES_C*4)/256, 256>>>(rad_w1, rad_b1, rad_w2, rad_b2,
                                                w_si1, w_si2_0, w_si2_1);

  edge1_kernel<<<EB, ET>>>(positions, node_feat, senders, receivers);
  node_gate_kernel<1><<<NB, 256>>>();

  edge2_kernel<<<EB, ET>>>(senders, receivers, w_si3_0, w_si3_1);
  node_gate_kernel<2><<<NB, 256>>>();

  edge3_kernel<<<EB, ET>>>(senders, receivers, w_si4);

  pool_kernel<<<(N_GRAPH_C*32)/256, 256>>>(w_out, out);
}

// round 8
// speedup vs baseline: 1.2710x; 1.2710x over previous
#include <cuda_runtime.h>

#define N_GRAPH_C 4096
#define N_NODES_C 131072
#define N_EDGES_C 2097152

#define NT 1024
#define TBL_SCALE 128.0f             // NT / 8.0
#define TBL_INV_SCALE 0.0078125f     // 8.0 / NT
#define INV_SQRT3_C 0.5773502691896258f
#define INV_SQRT2_C 0.7071067811865476f

// ---------------- persistent device scratch ----------------
// Small radial tables (values at knots; edge kernels lerp row k against row k+1):
//  g_T1v[k*2+{0,1}]  = {A0,A1}(k)   (layer1, w_si1/w_si2 folded in)
//  g_T2v[k*5+{0..4}] = {R2,R3,R4,R5/sqrt3,R6/sqrt2}(k)
//  g_T3v[k*2+{0,1}]  = {R7,R8/sqrt3}(k)
__device__ float4 g_T1v[NT*2];
__device__ float4 g_T2v[NT*5];
__device__ float4 g_T3v[NT*2];
// Padded positions: {x, y, z, node_feat}
__device__ float4 g_pos4[N_NODES_C];
// Per-edge cached geometry: {ux, uy, uz, fid = d*TBL_SCALE}
__device__ float4 g_geo[N_EDGES_C];
// Accumulators (post self-interaction, pre-gate)
__device__ float4 g_acc1[N_NODES_C*4];
__device__ float4 g_acc2[N_NODES_C*4];
__device__ float4 g_acc3[N_NODES_C];
// Gated features: [0..3]=l0, [4..15]=l1 (layout i*3+m)
__device__ float4 g_feats1[N_NODES_C*4];
__device__ float4 g_feats2[N_NODES_C*4];

// ---------------- helpers ----------------
__device__ __forceinline__ void red_v4(float4* p, float a, float b, float c, float d){
  asm volatile("red.global.add.v4.f32 [%0], {%1,%2,%3,%4};"
               :: "l"(p), "f"(a), "f"(b), "f"(c), "f"(d) : "memory");
}
__device__ __forceinline__ float siluf(float x){ return x / (1.f + __expf(-x)); }
__device__ __forceinline__ float sigmf(float x){ return 1.f / (1.f + __expf(-x)); }
__device__ __forceinline__ float4 lerp4(float4 a, float4 b, float w){
  return make_float4(fmaf(w, b.x-a.x, a.x), fmaf(w, b.y-a.y, a.y),
                     fmaf(w, b.z-a.z, a.z), fmaf(w, b.w-a.w, a.w));
}
__device__ __forceinline__ void tbl_decode(float fid, int& i0, float& w){
  int i = (int)fid;
  i = (i > NT-2) ? (NT-2) : i;
  i0 = i;
  w = fminf(fid - (float)i, 1.f);
}

// ---------------- radial MLP eval (table build only) ----------------
__device__ __forceinline__ void eval_R(int p, float d,
                                       const float* __restrict__ rw1, const float* __restrict__ rb1,
                                       const float* __restrict__ rw2, const float* __restrict__ rb2,
                                       float R[4])
{
  float rbf[8];
  #pragma unroll
  for (int j=0;j<8;j++){ float t = d - 0.5f*(float)j; rbf[j] = __expf(-4.f*t*t); }
  float h[8];
  #pragma unroll
  for (int j=0;j<8;j++){
    float a = __ldg(rb1 + p*8 + j);
    #pragma unroll
    for (int b=0;b<8;b++) a = fmaf(rbf[b], __ldg(rw1 + p*64 + b*8 + j), a);
    h[j] = fmaxf(a, 0.f);
  }
  #pragma unroll
  for (int c=0;c<4;c++){
    float a = __ldg(rb2 + p*4 + c);
    #pragma unroll
    for (int j=0;j<8;j++) a = fmaf(h[j], __ldg(rw2 + p*32 + j*4 + c), a);
    R[c] = a;
  }
}

// ---------------- build tables + pad positions + zero acc1 (fused) ----------------
__global__ void build_zero_kernel(const float* __restrict__ pos, const float* __restrict__ nf,
                                  const float* __restrict__ rw1, const float* __restrict__ rb1,
                                  const float* __restrict__ rw2, const float* __restrict__ rb2,
                                  const float* __restrict__ wsi1,
                                  const float* __restrict__ w20, const float* __restrict__ w21)
{
  int idx = blockIdx.x*blockDim.x + threadIdx.x;
  if (idx < N_NODES_C*4) g_acc1[idx] = make_float4(0.f,0.f,0.f,0.f);
  if (idx < N_NODES_C)
    g_pos4[idx] = make_float4(__ldg(pos+3*idx), __ldg(pos+3*idx+1),
                              __ldg(pos+3*idx+2), __ldg(nf+idx));
  if (idx >= 9*NT) return;
  int p = idx / NT;
  int k = idx - p*NT;
  float d0 = (float)k * TBL_INV_SCALE;
  float Ra[4];
  eval_R(p, d0, rw1, rb1, rw2, rb2, Ra);

  if (p <= 1){
    const float* W = (p==0) ? w20 : w21;
    float Av[4];
    #pragma unroll
    for (int o=0;o<4;o++){
      float av = 0.f;
      #pragma unroll
      for (int c=0;c<4;c++)
        av = fmaf(__ldg(W + o*4 + c) * __ldg(wsi1 + c), Ra[c], av);
      Av[o] = av;
    }
    g_T1v[k*2 + p] = make_float4(Av[0],Av[1],Av[2],Av[3]);
  } else if (p <= 6){
    float s = (p==5) ? INV_SQRT3_C : ((p==6) ? INV_SQRT2_C : 1.f);
    g_T2v[k*5 + (p-2)] = make_float4(Ra[0]*s, Ra[1]*s, Ra[2]*s, Ra[3]*s);
  } else {
    float s = (p==8) ? INV_SQRT3_C : 1.f;
    g_T3v[k*2 + (p-7)] = make_float4(Ra[0]*s, Ra[1]*s, Ra[2]*s, Ra[3]*s);
  }
}

// ---------------- layer 1 edge kernel (computes + caches geometry) ----------------
__global__ __launch_bounds__(256)
void edge1_kernel(const int* __restrict__ snd, const int* __restrict__ rcv)
{
  extern __shared__ float4 sT[];                 // NT*2 = 32KB
  for (int i = threadIdx.x; i < NT*2; i += blockDim.x) sT[i] = g_T1v[i];
  __syncthreads();

  int stride = gridDim.x*blockDim.x;
  for (int e = blockIdx.x*blockDim.x + threadIdx.x; e < N_EDGES_C; e += stride){
    int s = __ldg(snd+e), r = __ldg(rcv+e);
    float4 ps = __ldg(&g_pos4[s]);
    float4 pr = __ldg(&g_pos4[r]);
    float nv = ps.w;
    float dx=pr.x-ps.x, dy=pr.y-ps.y, dz=pr.z-ps.z;
    float d = sqrtf(dx*dx + dy*dy + dz*dz);
    float inv = 1.f / fmaxf(d, 1e-9f);
    float ux = dx*inv, uy = dy*inv, uz = dz*inv;
    float fid = d * TBL_SCALE;
    g_geo[e] = make_float4(ux, uy, uz, fid);

    int i0; float w; tbl_decode(fid, i0, w);
    float4 A0 = lerp4(sT[i0*2+0], sT[i0*2+2], w);
    float4 A1 = lerp4(sT[i0*2+1], sT[i0*2+3], w);
    float4* dst = &g_acc1[(size_t)r*4];
    red_v4(dst, nv*A0.x, nv*A0.y, nv*A0.z, nv*A0.w);
    float t0=nv*A1.x, t1=nv*A1.y, t2=nv*A1.z, t3=nv*A1.w;
    red_v4(dst+1, t0*ux, t0*uy, t0*uz, t1*ux);
    red_v4(dst+2, t1*uy, t1*uz, t2*ux, t2*uy);
    red_v4(dst+3, t2*uz, t3*ux, t3*uy, t3*uz);
  }
}

// ---------------- layer 2 edge kernel ----------------
__global__ __launch_bounds__(256)
void edge2_kernel(const int* __restrict__ snd, const int* __restrict__ rcv,
                  const float* __restrict__ w30, const float* __restrict__ w31)
{
  extern __shared__ float4 sT[];                 // NT*5 = 80KB
  for (int i = threadIdx.x; i < NT*5; i += blockDim.x) sT[i] = g_T2v[i];
  __syncthreads();

  float W0[32];
  #pragma unroll
  for (int i=0;i<32;i++) W0[i] = __ldg(w30+i);
  float W1[48];
  #pragma unroll
  for (int i=0;i<48;i++) W1[i] = __ldg(w31+i);

  int stride = gridDim.x*blockDim.x;
  for (int e = blockIdx.x*blockDim.x + threadIdx.x; e < N_EDGES_C; e += stride){
    int s = __ldg(snd+e), r = __ldg(rcv+e);
    float4 geo = __ldg(&g_geo[e]);
    float ux = geo.x, uy = geo.y, uz = geo.z;
    int i0; float w; tbl_decode(geo.w, i0, w);

    float4 f0v = __ldg(&g_feats1[(size_t)s*4]);
    float4 fa  = __ldg(&g_feats1[(size_t)s*4+1]);
    float4 fb  = __ldg(&g_feats1[(size_t)s*4+2]);
    float4 fc  = __ldg(&g_feats1[(size_t)s*4+3]);
    float x0[4]  = {f0v.x,f0v.y,f0v.z,f0v.w};
    float x1[12] = {fa.x,fa.y,fa.z,fa.w, fb.x,fb.y,fb.z,fb.w, fc.x,fc.y,fc.z,fc.w};

    const float4* lo = &sT[i0*5];
    const float4* hi = lo + 5;
    float4 r2 = lerp4(lo[0], hi[0], w);
    float4 r3 = lerp4(lo[1], hi[1], w);
    float4 r4 = lerp4(lo[2], hi[2], w);
    float4 r5 = lerp4(lo[3], hi[3], w);   // pre-scaled 1/sqrt3
    float4 r6 = lerp4(lo[4], hi[4], w);   // pre-scaled 1/sqrt2
    float R2[4]={r2.x,r2.y,r2.z,r2.w}, R3[4]={r3.x,r3.y,r3.z,r3.w};
    float R4[4]={r4.x,r4.y,r4.z,r4.w}, R5[4]={r5.x,r5.y,r5.z,r5.w};
    float R6[4]={r6.x,r6.y,r6.z,r6.w};

    float dot_[4];
    #pragma unroll
    for (int i=0;i<4;i++)
      dot_[i] = x1[i*3]*ux + x1[i*3+1]*uy + x1[i*3+2]*uz;

    // l0: W0 @ [R2*x0 ; R5*dot/sqrt3]
    float ma[4], mb[4];
    #pragma unroll
    for (int i=0;i<4;i++){ ma[i] = R2[i]*x0[i]; mb[i] = R5[i]*dot_[i]; }
    float o0[4];
    #pragma unroll
    for (int o=0;o<4;o++){
      float a = 0.f;
      #pragma unroll
      for (int i=0;i<4;i++){
        a = fmaf(W0[o*8+i],   ma[i], a);
        a = fmaf(W0[o*8+4+i], mb[i], a);
      }
      o0[o] = a;
    }
    float4* dst = &g_acc2[(size_t)r*4];
    red_v4(dst, o0[0], o0[1], o0[2], o0[3]);

    // l1: W1 @ [R3*x0*u ; R4*x1 ; R6*cross(x1,u)/sqrt2]
    float c3[4], e4[12], e6[12];
    #pragma unroll
    for (int i=0;i<4;i++){
      c3[i] = R3[i]*x0[i];
      e4[i*3+0]=R4[i]*x1[i*3+0]; e4[i*3+1]=R4[i]*x1[i*3+1]; e4[i*3+2]=R4[i]*x1[i*3+2];
      e6[i*3+0]=R6[i]*x1[i*3+0]; e6[i*3+1]=R6[i]*x1[i*3+1]; e6[i*3+2]=R6[i]*x1[i*3+2];
    }
    float o1[12];
    #pragma unroll
    for (int o=0;o<4;o++){
      float ta=0.f, zx=0.f, zy=0.f, zz=0.f, yx=0.f, yy=0.f, yz=0.f;
      #pragma unroll
      for (int i=0;i<4;i++){
        ta = fmaf(W1[o*12+i], c3[i], ta);
        float w4 = W1[o*12+4+i], w6 = W1[o*12+8+i];
        zx = fmaf(w4, e4[i*3+0], zx); zy = fmaf(w4, e4[i*3+1], zy); zz = fmaf(w4, e4[i*3+2], zz);
        yx = fmaf(w6, e6[i*3+0], yx); yy = fmaf(w6, e6[i*3+1], yy); yz = fmaf(w6, e6[i*3+2], yz);
      }
      float cx = yy*uz - yz*uy;
      float cy = yz*ux - yx*uz;
      float cz = yx*uy - yy*ux;
      o1[o*3+0] = fmaf(ta, ux, zx + cx);
      o1[o*3+1] = fmaf(ta, uy, zy + cy);
      o1[o*3+2] = fmaf(ta, uz, zz + cz);
    }
    red_v4(dst+1, o1[0], o1[1], o1[2],  o1[3]);
    red_v4(dst+2, o1[4], o1[5], o1[6],  o1[7]);
    red_v4(dst+3, o1[8], o1[9], o1[10], o1[11]);
  }
}

// ---------------- layer 3 edge kernel ----------------
__global__ __launch_bounds__(256)
void edge3_kernel(const int* __restrict__ snd, const int* __restrict__ rcv,
                  const float* __restrict__ w4)
{
  extern __shared__ float4 sT[];                 // NT*2 = 32KB
  for (int i = threadIdx.x; i < NT*2; i += blockDim.x) sT[i] = g_T3v[i];
  __syncthreads();

  float W4[32];
  #pragma unroll
  for (int i=0;i<32;i++) W4[i] = __ldg(w4+i);

  int stride = gridDim.x*blockDim.x;
  for (int e = blockIdx.x*blockDim.x + threadIdx.x; e < N_EDGES_C; e += stride){
    int s = __ldg(snd+e), r = __ldg(rcv+e);
    float4 geo = __ldg(&g_geo[e]);
    float ux = geo.x, uy = geo.y, uz = geo.z;
    int i0; float w; tbl_decode(geo.w, i0, w);

    float4 f0v = __ldg(&g_feats2[(size_t)s*4]);
    float4 fa  = __ldg(&g_feats2[(size_t)s*4+1]);
    float4 fb  = __ldg(&g_feats2[(size_t)s*4+2]);
    float4 fc  = __ldg(&g_feats2[(size_t)s*4+3]);
    float x0[4]  = {f0v.x,f0v.y,f0v.z,f0v.w};
    float x1[12] = {fa.x,fa.y,fa.z,fa.w, fb.x,fb.y,fb.z,fb.w, fc.x,fc.y,fc.z,fc.w};

    float4 r7 = lerp4(sT[i0*2+0], sT[i0*2+2], w);
    float4 r8 = lerp4(sT[i0*2+1], sT[i0*2+3], w);  // pre-scaled 1/sqrt3
    float R7[4]={r7.x,r7.y,r7.z,r7.w}, R8[4]={r8.x,r8.y,r8.z,r8.w};

    float dot_[4];
    #pragma unroll
    for (int i=0;i<4;i++)
      dot_[i] = x1[i*3]*ux + x1[i*3+1]*uy + x1[i*3+2]*uz;

    float o[4];
    #pragma unroll
    for (int oo=0;oo<4;oo++){
      float a = 0.f;
      #pragma unroll
      for (int i=0;i<4;i++){
        a = fmaf(W4[oo*8+i],   R7[i]*x0[i],   a);
        a = fmaf(W4[oo*8+4+i], R8[i]*dot_[i], a);
      }
      o[oo] = a;
    }
    red_v4(&g_acc3[r], o[0], o[1], o[2], o[3]);
  }
}

// ---------------- node gating (layers 1 & 2); zeroes next accumulator ----------------
template<int L>
__global__ void node_gate_kernel(){
  int n = blockIdx.x*blockDim.x + threadIdx.x;
  if (n >= N_NODES_C) return;
  const float4* acc = (L==1) ? g_acc1 : g_acc2;
  float4* fe = (L==1) ? g_feats1 : g_feats2;
  float4 s0 = acc[(size_t)n*4+0];
  float4 s1 = acc[(size_t)n*4+1];
  float4 s2 = acc[(size_t)n*4+2];
  float4 s3 = acc[(size_t)n*4+3];
  float f1[12] = {s1.x,s1.y,s1.z,s1.w, s2.x,s2.y,s2.z,s2.w, s3.x,s3.y,s3.z,s3.w};
  float o1[12];
  #pragma unroll
  for (int o=0;o<4;o++){
    float a=f1[o*3], b=f1[o*3+1], c=f1[o*3+2];
    float nrm = sqrtf(a*a + b*b + c*c);
    float sg = sigmf(nrm);
    o1[o*3+0]=a*sg; o1[o*3+1]=b*sg; o1[o*3+2]=c*sg;
  }
  fe[(size_t)n*4+0] = make_float4(siluf(s0.x), siluf(s0.y), siluf(s0.z), siluf(s0.w));
  fe[(size_t)n*4+1] = make_float4(o1[0],o1[1],o1[2],o1[3]);
  fe[(size_t)n*4+2] = make_float4(o1[4],o1[5],o1[6],o1[7]);
  fe[(size_t)n*4+3] = make_float4(o1[8],o1[9],o1[10],o1[11]);
  float4 z = make_float4(0.f,0.f,0.f,0.f);
  if (L==1){
    g_acc2[(size_t)n*4+0]=z; g_acc2[(size_t)n*4+1]=z;
    g_acc2[(size_t)n*4+2]=z; g_acc2[(size_t)n*4+3]=z;
  } else {
    g_acc3[n] = z;
  }
}

// ---------------- graph pooling (+silu gate of layer 3) + output projection ----------------
__global__ void pool_kernel(const float* __restrict__ w_out, float* __restrict__ out){
  int gw   = (blockIdx.x*blockDim.x + threadIdx.x) >> 5;
  int lane = threadIdx.x & 31;
  if (gw >= N_GRAPH_C) return;
  float4 a = g_acc3[(size_t)gw*32 + lane];
  float4 v = make_float4(siluf(a.x), siluf(a.y), siluf(a.z), siluf(a.w));
  #pragma unroll
  for (int off=16; off; off>>=1){
    v.x += __shfl_down_sync(0xFFFFFFFFu, v.x, off);
    v.y += __shfl_down_sync(0xFFFFFFFFu, v.y, off);
    v.z += __shfl_down_sync(0xFFFFFFFFu, v.z, off);
    v.w += __shfl_down_sync(0xFFFFFFFFu, v.w, off);
  }
  if (lane == 0){
    #pragma unroll
    for (int j=0;j<8;j++){
      out[gw*8+j] = __ldg(w_out+j*4+0)*v.x + __ldg(w_out+j*4+1)*v.y
                  + __ldg(w_out+j*4+2)*v.z + __ldg(w_out+j*4+3)*v.w;
    }
  }
}

// ---------------- launch ----------------
extern "C" void kernel_launch(void* const* d_in, const int* in_sizes, int n_in,
                              void* d_out, int out_size)
{
  const float* positions = (const float*)d_in[0];
  const float* node_feat = (const float*)d_in[1];
  const float* w_si1     = (const float*)d_in[2];
  const float* w_si2_0   = (const float*)d_in[3];
  const float* w_si2_1   = (const float*)d_in[4];
  const float* w_si3_0   = (const float*)d_in[5];
  const float* w_si3_1   = (const float*)d_in[6];
  const float* w_si4     = (const float*)d_in[7];
  const float* w_out     = (const float*)d_in[8];
  const float* rad_w1    = (const float*)d_in[9];
  const float* rad_b1    = (const float*)d_in[10];
  const float* rad_w2    = (const float*)d_in[11];
  const float* rad_b2    = (const float*)d_in[12];
  const int*   senders   = (const int*)d_in[13];
  const int*   receivers = (const int*)d_in[14];
  float* out = (float*)d_out;

  const int SM1 = NT*2*sizeof(float4);   // 32KB
  const int SM2 = NT*5*sizeof(float4);   // 80KB
  const int SM3 = NT*2*sizeof(float4);   // 32KB
  cudaFuncSetAttribute(edge1_kernel, cudaFuncAttributeMaxDynamicSharedMemorySize, SM1);
  cudaFuncSetAttribute(edge2_kernel, cudaFuncAttributeMaxDynamicSharedMemorySize, SM2);
  cudaFuncSetAttribute(edge3_kernel, cudaFuncAttributeMaxDynamicSharedMemorySize, SM3);

  const int NB = N_NODES_C / 256;

  build_zero_kernel<<<(N_NODES_C*4)/256, 256>>>(positions, node_feat,
                                                rad_w1, rad_b1, rad_w2, rad_b2,
                                                w_si1, w_si2_0, w_si2_1);

  edge1_kernel<<<1024, 256, SM1>>>(senders, receivers);
  node_gate_kernel<1><<<NB, 256>>>();

  edge2_kernel<<<592, 256, SM2>>>(senders, receivers, w_si3_0, w_si3_1);
  node_gate_kernel<2><<<NB, 256>>>();

  edge3_kernel<<<1024, 256, SM3>>>(senders, receivers, w_si4);

  pool_kernel<<<(N_GRAPH_C*32)/256, 256>>>(w_out, out);
}